// round 4
// baseline (speedup 1.0000x reference)
#include <cuda_runtime.h>

// ---------------------------------------------------------------------------
// edge_exists_predictor — fully linear network folded to scalar-per-node
// propagation (see R2). R3 changes:
//   * edge_index packed to int32 device arrays ONCE (fits in L2, reused by
//     both scatter passes) with degree atomics fused into the same pass
//   * 4 edges/thread int4-vectorized scatters (MLP for L2 latency hiding)
//   * 12 -> 8 kernel launches (fold+detect+out-init fused; dinv fused into
//     t0; final layer fused with pooling)
// ---------------------------------------------------------------------------

#define NMAX 100000
#define EMAX 3200000
#define FIN  64

__device__ int   g_is64;
__device__ int   g_deg[NMAX];
__device__ float g_dinv[NMAX];
__device__ float g_t[NMAX];
__device__ float g_p[NMAX];
__device__ float g_acc1[NMAX];
__device__ float g_acc2[NMAX];
__device__ float g_w1c[FIN];
__device__ float g_cst[3];        // c1, c2, cb
__device__ int   g_src[EMAX];
__device__ int   g_dst[EMAX];

// --- prep: dtype detect + fold all weights + init out with cb ---------------
__global__ void k_prep(const int* ei32,
                       const float* W1, const float* b1,
                       const float* W2, const float* b2,
                       const float* Wf1, const float* bf1,
                       const float* Wf2, const float* bf2,
                       const float* Wf3, const float* bf3,
                       const float* Wo,  const float* bo,
                       float* out, int G) {
    __shared__ float v3[20], v2[30], v1[50], w2c[60];
    __shared__ float cb_s;
    int t = threadIdx.x;
    if (t == 0) {
        int z = ei32[1] | ei32[3] | ei32[5] | ei32[7] | ei32[9] | ei32[11];
        g_is64 = (z == 0) ? 1 : 0;
    }
    if (t < 20) { float s = 0.f; for (int j = 0; j < 10; j++) s += Wf3[t*10+j] * Wo[j]; v3[t] = s; }
    __syncthreads();
    if (t < 30) { float s = 0.f; for (int j = 0; j < 20; j++) s += Wf2[t*20+j] * v3[j]; v2[t] = s; }
    __syncthreads();
    if (t < 50) { float s = 0.f; for (int j = 0; j < 30; j++) s += Wf1[t*30+j] * v2[j]; v1[t] = s; }
    __syncthreads();
    if (t < 60) { float s = 0.f; for (int j = 0; j < 50; j++) s += W2[t*50+j] * v1[j]; w2c[t] = s; }
    __syncthreads();
    if (t < 64) { float s = 0.f; for (int j = 0; j < 60; j++) s += W1[t*60+j] * w2c[j]; g_w1c[t] = s; }
    if (t == 0) {
        float c1 = 0.f; for (int j = 0; j < 60; j++) c1 += b1[j] * w2c[j];
        float c2 = 0.f; for (int j = 0; j < 50; j++) c2 += b2[j] * v1[j];
        float cb = bo[0];
        for (int j = 0; j < 30; j++) cb += bf1[j] * v2[j];
        for (int j = 0; j < 20; j++) cb += bf2[j] * v3[j];
        for (int j = 0; j < 10; j++) cb += bf3[j] * Wo[j];
        g_cst[0] = c1; g_cst[1] = c2; g_cst[2] = cb; cb_s = cb;
    }
    __syncthreads();
    if (t < G) out[t] = cb_s;
}

__global__ void k_zero(int n) {
    int i = blockIdx.x * blockDim.x + threadIdx.x;
    if (i < n) { g_deg[i] = 0; g_acc1[i] = 0.f; g_acc2[i] = 0.f; }
}

// --- pack edge_index -> int32 arrays + degree atomics (one int64 read pass) -
__global__ void k_pack(const void* ei, int E) {
    int i = (blockIdx.x * blockDim.x + threadIdx.x) * 2;
    if (i >= E) return;
    if (i + 1 < E) {
        int s0, s1, d0, d1;
        if (g_is64) {
            const long long* p = (const long long*)ei;
            longlong2 sv = *(const longlong2*)(p + i);
            longlong2 dv = *(const longlong2*)(p + E + i);
            s0 = (int)sv.x; s1 = (int)sv.y; d0 = (int)dv.x; d1 = (int)dv.y;
        } else {
            const int* p = (const int*)ei;
            int2 sv = *(const int2*)(p + i);
            int2 dv = *(const int2*)(p + E + i);
            s0 = sv.x; s1 = sv.y; d0 = dv.x; d1 = dv.y;
        }
        g_src[i] = s0; g_src[i+1] = s1;
        g_dst[i] = d0; g_dst[i+1] = d1;
        atomicAdd(&g_deg[d0], 1);
        atomicAdd(&g_deg[d1], 1);
    } else {
        int s, d;
        if (g_is64) {
            const long long* p = (const long long*)ei;
            s = (int)p[i]; d = (int)p[E + i];
        } else {
            const int* p = (const int*)ei;
            s = p[i]; d = p[E + i];
        }
        g_src[i] = s; g_dst[i] = d;
        atomicAdd(&g_deg[d], 1);
    }
}

// --- t0 = x . w1c (warp/node) + dinv = rsqrt(deg+1), fused ------------------
__global__ void k_t0(const float* __restrict__ x, int n) {
    int gw   = (blockIdx.x * blockDim.x + threadIdx.x) >> 5;
    int lane = threadIdx.x & 31;
    if (gw >= n) return;
    float2 xv = ((const float2*)x)[gw * 32 + lane];
    float acc = xv.x * g_w1c[2*lane] + xv.y * g_w1c[2*lane + 1];
    #pragma unroll
    for (int o = 16; o; o >>= 1) acc += __shfl_xor_sync(0xffffffffu, acc, o);
    if (lane == 0) {
        float di = rsqrtf((float)(g_deg[gw] + 1));
        g_dinv[gw] = di;
        g_t[gw]    = acc;
        g_p[gw]    = di * acc;
    }
}

// --- scatter: acc[dst] += p[src], 4 edges/thread, int4 index loads ----------
__global__ void k_scatter(int E, int layer) {
    float* acc = layer ? g_acc2 : g_acc1;
    int i = (blockIdx.x * blockDim.x + threadIdx.x) * 4;
    if (i >= E) return;
    if (i + 3 < E) {
        int4 s = *(const int4*)(g_src + i);
        int4 d = *(const int4*)(g_dst + i);
        float p0 = g_p[s.x], p1 = g_p[s.y], p2 = g_p[s.z], p3 = g_p[s.w];
        atomicAdd(&acc[d.x], p0);
        atomicAdd(&acc[d.y], p1);
        atomicAdd(&acc[d.z], p2);
        atomicAdd(&acc[d.w], p3);
    } else {
        for (int k = i; k < E; k++)
            atomicAdd(&acc[g_dst[k]], g_p[g_src[k]]);
    }
}

// --- finalize layer 1: t = dinv*(acc1 + dinv*t) + c1; p = dinv*t ------------
__global__ void k_fin0(int n) {
    int i = blockIdx.x * blockDim.x + threadIdx.x;
    if (i >= n) return;
    float di = g_dinv[i];
    float t  = di * (g_acc1[i] + di * g_t[i]) + g_cst[0];
    g_t[i] = t;
    g_p[i] = di * t;
}

// --- finalize layer 2 + pooled sum per graph (batch sorted) -----------------
__global__ void k_finpool(const void* batch, float* out, int n) {
    int i    = blockIdx.x * blockDim.x + threadIdx.x;
    int lane = threadIdx.x & 31;
    int ic   = i < n ? i : (n - 1);
    int gid  = g_is64 ? (int)((const long long*)batch)[ic]
                      : ((const int*)batch)[ic];
    float v = 0.f;
    if (i < n) {
        float di = g_dinv[i];
        v = di * (g_acc2[i] + di * g_t[i]) + g_cst[1];
    }
    int g0   = __shfl_sync(0xffffffffu, gid, 0);
    bool uni = __all_sync(0xffffffffu, gid == g0);
    if (uni) {
        #pragma unroll
        for (int o = 16; o; o >>= 1) v += __shfl_xor_sync(0xffffffffu, v, o);
        if (lane == 0) atomicAdd(&out[g0], v);
    } else {
        atomicAdd(&out[gid], v);
    }
}

extern "C" void kernel_launch(void* const* d_in, const int* in_sizes, int n_in,
                              void* d_out, int out_size) {
    const float* x     = (const float*)d_in[0];
    const void*  ei    = d_in[1];
    const void*  batch = d_in[2];
    const float* W1  = (const float*)d_in[3],  *b1  = (const float*)d_in[4];
    const float* W2  = (const float*)d_in[5],  *b2  = (const float*)d_in[6];
    const float* Wf1 = (const float*)d_in[7],  *bf1 = (const float*)d_in[8];
    const float* Wf2 = (const float*)d_in[9],  *bf2 = (const float*)d_in[10];
    const float* Wf3 = (const float*)d_in[11], *bf3 = (const float*)d_in[12];
    const float* Wo  = (const float*)d_in[13], *bo  = (const float*)d_in[14];
    float* out = (float*)d_out;

    int E = in_sizes[1] / 2;
    int n = in_sizes[2];
    int G = out_size;

    int nb = (n + 255) / 256;

    k_prep<<<1, 256>>>((const int*)ei, W1, b1, W2, b2,
                       Wf1, bf1, Wf2, bf2, Wf3, bf3, Wo, bo, out, G);
    k_zero<<<nb, 256>>>(n);
    k_pack<<<(E/2 + 255) / 256, 256>>>(ei, E);
    k_t0<<<(n + 7) / 8, 256>>>(x, n);
    k_scatter<<<((E + 3) / 4 + 255) / 256, 256>>>(E, 0);
    k_fin0<<<nb, 256>>>(n);
    k_scatter<<<((E + 3) / 4 + 255) / 256, 256>>>(E, 1);
    k_finpool<<<nb, 256>>>(batch, out, n);
}

// round 6
// speedup vs baseline: 1.0260x; 1.0260x over previous
#include <cuda_runtime.h>

// ---------------------------------------------------------------------------
// edge_exists_predictor — linear network folded to scalar-per-node propagation.
//   * whole net is linear: fold all weights into w1c[64] + 3 scalars
//   * t0: 4 lanes/node, 8 nodes/warp, MLP=4 float4 loads, 2 shfl steps
//   * edge_index packed to int32 once (L2-resident), degree fused in
//   * scatters: 8 edges/thread, __ldg gathers, atomicAdd scatter
//   * 7 kernel launches total
// ---------------------------------------------------------------------------

#define NMAX 100000
#define EMAX 3200000

__device__ int   g_is64;
__device__ int   g_deg[NMAX];
__device__ float g_dinv[NMAX];
__device__ float g_t[NMAX];
__device__ float g_p[NMAX];
__device__ float g_acc1[NMAX];
__device__ float g_acc2[NMAX];
__device__ float g_w1c[64];
__device__ float g_cst[3];        // c1, c2, cb
__device__ int   g_src[EMAX];
__device__ int   g_dst[EMAX];

// --- init: zero state (all blocks) + dtype detect + weight fold (block 0) ---
__global__ void k_init(const int* ei32,
                       const float* W1, const float* b1,
                       const float* W2, const float* b2,
                       const float* Wf1, const float* bf1,
                       const float* Wf2, const float* bf2,
                       const float* Wf3, const float* bf3,
                       const float* Wo,  const float* bo,
                       float* out, int G, int n) {
    int i = blockIdx.x * blockDim.x + threadIdx.x;
    if (i < n) { g_deg[i] = 0; g_acc1[i] = 0.f; g_acc2[i] = 0.f; }

    if (blockIdx.x == 0) {
        __shared__ float v3[20], v2[30], v1[50], w2c[60];
        __shared__ float cb_s;
        int t = threadIdx.x;
        if (t == 0) {
            int z = ei32[1] | ei32[3] | ei32[5] | ei32[7] | ei32[9] | ei32[11];
            g_is64 = (z == 0) ? 1 : 0;
        }
        if (t < 20) { float s = 0.f; for (int j = 0; j < 10; j++) s += Wf3[t*10+j] * Wo[j]; v3[t] = s; }
        __syncthreads();
        if (t < 30) { float s = 0.f; for (int j = 0; j < 20; j++) s += Wf2[t*20+j] * v3[j]; v2[t] = s; }
        __syncthreads();
        if (t < 50) { float s = 0.f; for (int j = 0; j < 30; j++) s += Wf1[t*30+j] * v2[j]; v1[t] = s; }
        __syncthreads();
        if (t < 60) { float s = 0.f; for (int j = 0; j < 50; j++) s += W2[t*50+j] * v1[j]; w2c[t] = s; }
        __syncthreads();
        if (t < 64) { float s = 0.f; for (int j = 0; j < 60; j++) s += W1[t*60+j] * w2c[j]; g_w1c[t] = s; }
        if (t == 0) {
            float c1 = 0.f; for (int j = 0; j < 60; j++) c1 += b1[j] * w2c[j];
            float c2 = 0.f; for (int j = 0; j < 50; j++) c2 += b2[j] * v1[j];
            float cb = bo[0];
            for (int j = 0; j < 30; j++) cb += bf1[j] * v2[j];
            for (int j = 0; j < 20; j++) cb += bf2[j] * v3[j];
            for (int j = 0; j < 10; j++) cb += bf3[j] * Wo[j];
            g_cst[0] = c1; g_cst[1] = c2; g_cst[2] = cb; cb_s = cb;
        }
        __syncthreads();
        if (t < G) out[t] = cb_s;
    }
}

// --- pack edge_index -> int32 + degree atomics, 4 edges/thread --------------
__global__ void k_pack(const void* ei, int E) {
    int i = (blockIdx.x * blockDim.x + threadIdx.x) * 4;
    if (i >= E) return;
    if (i + 3 < E) {
        int4 sv, dv;
        if (g_is64) {
            const long long* p = (const long long*)ei;
            longlong2 sa = *(const longlong2*)(p + i);
            longlong2 sb = *(const longlong2*)(p + i + 2);
            longlong2 da = *(const longlong2*)(p + E + i);
            longlong2 db = *(const longlong2*)(p + E + i + 2);
            sv = make_int4((int)sa.x, (int)sa.y, (int)sb.x, (int)sb.y);
            dv = make_int4((int)da.x, (int)da.y, (int)db.x, (int)db.y);
        } else {
            const int* p = (const int*)ei;
            sv = *(const int4*)(p + i);
            dv = *(const int4*)(p + E + i);
        }
        *(int4*)(g_src + i) = sv;
        *(int4*)(g_dst + i) = dv;
        atomicAdd(&g_deg[dv.x], 1);
        atomicAdd(&g_deg[dv.y], 1);
        atomicAdd(&g_deg[dv.z], 1);
        atomicAdd(&g_deg[dv.w], 1);
    } else {
        for (int k = i; k < E; k++) {
            int s, d;
            if (g_is64) {
                const long long* p = (const long long*)ei;
                s = (int)p[k]; d = (int)p[E + k];
            } else {
                const int* p = (const int*)ei;
                s = p[k]; d = p[E + k];
            }
            g_src[k] = s; g_dst[k] = d;
            atomicAdd(&g_deg[d], 1);
        }
    }
}

// --- t0 = x . w1c : 4 lanes/node, 8 nodes/warp, float4 loads, 2 shfl steps --
// All lanes of a warp execute the shuffles; out-of-range nodes are clamped
// (their lanes compute garbage but never store).
__global__ void k_t0(const float* __restrict__ x, int n) {
    int gt    = blockIdx.x * blockDim.x + threadIdx.x;
    int w     = gt >> 5;
    int lane  = threadIdx.x & 31;
    int node  = w * 8 + (lane >> 2);
    int sub   = lane & 3;                 // covers floats [sub*16, sub*16+16)
    bool live = (node < n);
    int nc    = live ? node : (n - 1);    // clamp for safe loads

    const float4* xp = (const float4*)x + nc * 16 + sub * 4;
    float4 a = xp[0], b = xp[1], c = xp[2], d = xp[3];

    const float4* wv = (const float4*)g_w1c + sub * 4;
    float4 wa = wv[0], wb = wv[1], wc = wv[2], wd = wv[3];

    float s0 = a.x*wa.x + a.y*wa.y + a.z*wa.z + a.w*wa.w;
    float s1 = b.x*wb.x + b.y*wb.y + b.z*wb.z + b.w*wb.w;
    float s2 = c.x*wc.x + c.y*wc.y + c.z*wc.z + c.w*wc.w;
    float s3 = d.x*wd.x + d.y*wd.y + d.z*wd.z + d.w*wd.w;
    float acc = (s0 + s1) + (s2 + s3);

    acc += __shfl_xor_sync(0xffffffffu, acc, 1);
    acc += __shfl_xor_sync(0xffffffffu, acc, 2);

    if (live && sub == 0) {
        float di = rsqrtf((float)(g_deg[node] + 1));
        g_dinv[node] = di;
        g_t[node]    = acc;
        g_p[node]    = di * acc;
    }
}

// --- scatter: acc[dst] += p[src], 8 edges/thread ----------------------------
__global__ void k_scatter(int E, int layer) {
    float* acc = layer ? g_acc2 : g_acc1;
    int i = (blockIdx.x * blockDim.x + threadIdx.x) * 8;
    if (i >= E) return;
    if (i + 7 < E) {
        int4 s0 = *(const int4*)(g_src + i);
        int4 s1 = *(const int4*)(g_src + i + 4);
        int4 d0 = *(const int4*)(g_dst + i);
        int4 d1 = *(const int4*)(g_dst + i + 4);
        float p0 = __ldg(&g_p[s0.x]);
        float p1 = __ldg(&g_p[s0.y]);
        float p2 = __ldg(&g_p[s0.z]);
        float p3 = __ldg(&g_p[s0.w]);
        float p4 = __ldg(&g_p[s1.x]);
        float p5 = __ldg(&g_p[s1.y]);
        float p6 = __ldg(&g_p[s1.z]);
        float p7 = __ldg(&g_p[s1.w]);
        atomicAdd(&acc[d0.x], p0);
        atomicAdd(&acc[d0.y], p1);
        atomicAdd(&acc[d0.z], p2);
        atomicAdd(&acc[d0.w], p3);
        atomicAdd(&acc[d1.x], p4);
        atomicAdd(&acc[d1.y], p5);
        atomicAdd(&acc[d1.z], p6);
        atomicAdd(&acc[d1.w], p7);
    } else {
        for (int k = i; k < E; k++)
            atomicAdd(&acc[g_dst[k]], __ldg(&g_p[g_src[k]]));
    }
}

// --- finalize layer 1: t = dinv*(acc1 + dinv*t) + c1; p = dinv*t ------------
__global__ void k_fin0(int n) {
    int i = blockIdx.x * blockDim.x + threadIdx.x;
    if (i >= n) return;
    float di = g_dinv[i];
    float t  = di * (g_acc1[i] + di * g_t[i]) + g_cst[0];
    g_t[i] = t;
    g_p[i] = di * t;
}

// --- finalize layer 2 + pooled sum per graph (batch sorted) -----------------
__global__ void k_finpool(const void* batch, float* out, int n) {
    int i    = blockIdx.x * blockDim.x + threadIdx.x;
    int lane = threadIdx.x & 31;
    int ic   = i < n ? i : (n - 1);
    int gid  = g_is64 ? (int)((const long long*)batch)[ic]
                      : ((const int*)batch)[ic];
    float v = 0.f;
    if (i < n) {
        float di = g_dinv[i];
        v = di * (g_acc2[i] + di * g_t[i]) + g_cst[1];
    }
    int g0   = __shfl_sync(0xffffffffu, gid, 0);
    bool uni = __all_sync(0xffffffffu, gid == g0);
    if (uni) {
        #pragma unroll
        for (int o = 16; o; o >>= 1) v += __shfl_xor_sync(0xffffffffu, v, o);
        if (lane == 0) atomicAdd(&out[g0], v);
    } else {
        atomicAdd(&out[gid], v);
    }
}

extern "C" void kernel_launch(void* const* d_in, const int* in_sizes, int n_in,
                              void* d_out, int out_size) {
    const float* x     = (const float*)d_in[0];
    const void*  ei    = d_in[1];
    const void*  batch = d_in[2];
    const float* W1  = (const float*)d_in[3],  *b1  = (const float*)d_in[4];
    const float* W2  = (const float*)d_in[5],  *b2  = (const float*)d_in[6];
    const float* Wf1 = (const float*)d_in[7],  *bf1 = (const float*)d_in[8];
    const float* Wf2 = (const float*)d_in[9],  *bf2 = (const float*)d_in[10];
    const float* Wf3 = (const float*)d_in[11], *bf3 = (const float*)d_in[12];
    const float* Wo  = (const float*)d_in[13], *bo  = (const float*)d_in[14];
    float* out = (float*)d_out;

    int E = in_sizes[1] / 2;
    int n = in_sizes[2];
    int G = out_size;

    int nb = (n + 255) / 256;

    k_init<<<nb, 256>>>((const int*)ei, W1, b1, W2, b2,
                        Wf1, bf1, Wf2, bf2, Wf3, bf3, Wo, bo, out, G, n);
    k_pack<<<((E + 3) / 4 + 255) / 256, 256>>>(ei, E);
    k_t0<<<((n + 7) / 8 * 32 + 255) / 256, 256>>>(x, n);
    k_scatter<<<((E + 7) / 8 + 255) / 256, 256>>>(E, 0);
    k_fin0<<<nb, 256>>>(n);
    k_scatter<<<((E + 7) / 8 + 255) / 256, 256>>>(E, 1);
    k_finpool<<<nb, 256>>>(batch, out, n);
}

// round 7
// speedup vs baseline: 1.2401x; 1.2087x over previous
#include <cuda_runtime.h>

// ---------------------------------------------------------------------------
// edge_exists_predictor — linear net folded to scalar-per-node propagation.
// R6: dst-bucketed edge layout (512 buckets x 196 nodes) built once per
// replay; both GCN aggregations become dense-edge-read + random-gather +
// SMEM accumulation (no global atomics, no acc arrays, no degree atomics).
// ---------------------------------------------------------------------------

#define NMAX 100000
#define NB   512            // buckets
#define CAP  8192           // edges per bucket capacity (mean 6250)
#define EPB  4096           // edges staged per fill block

__device__ int   g_is64;
__device__ float g_dinv[NMAX];
__device__ float g_ta[NMAX];      // t0
__device__ float g_pa[NMAX];      // dinv * t0
__device__ float g_tb[NMAX];      // t1
__device__ float g_pb[NMAX];      // dinv * t1
__device__ float g_w1c[64];
__device__ float g_cst[3];        // c1, c2, cb
__device__ int   g_cur[NB];       // bucket fill cursors (= final counts)
__device__ int2  g_bedge[NB * CAP];   // bucketed (src, dst)

// --- init: zero cursors + dtype detect + weight fold + out init -------------
__global__ void k_init(const int* ei32,
                       const float* W1, const float* b1,
                       const float* W2, const float* b2,
                       const float* Wf1, const float* bf1,
                       const float* Wf2, const float* bf2,
                       const float* Wf3, const float* bf3,
                       const float* Wo,  const float* bo,
                       float* out, int G) {
    int i = blockIdx.x * blockDim.x + threadIdx.x;
    if (i < NB) g_cur[i] = 0;

    if (blockIdx.x == 0) {
        __shared__ float v3[20], v2[30], v1[50], w2c[60];
        __shared__ float cb_s;
        int t = threadIdx.x;
        if (t == 0) {
            int z = ei32[1] | ei32[3] | ei32[5] | ei32[7] | ei32[9] | ei32[11];
            g_is64 = (z == 0) ? 1 : 0;
        }
        if (t < 20) { float s = 0.f; for (int j = 0; j < 10; j++) s += Wf3[t*10+j] * Wo[j]; v3[t] = s; }
        __syncthreads();
        if (t < 30) { float s = 0.f; for (int j = 0; j < 20; j++) s += Wf2[t*20+j] * v3[j]; v2[t] = s; }
        __syncthreads();
        if (t < 50) { float s = 0.f; for (int j = 0; j < 30; j++) s += Wf1[t*30+j] * v2[j]; v1[t] = s; }
        __syncthreads();
        if (t < 60) { float s = 0.f; for (int j = 0; j < 50; j++) s += W2[t*50+j] * v1[j]; w2c[t] = s; }
        __syncthreads();
        if (t < 64) { float s = 0.f; for (int j = 0; j < 60; j++) s += W1[t*60+j] * w2c[j]; g_w1c[t] = s; }
        if (t == 0) {
            float c1 = 0.f; for (int j = 0; j < 60; j++) c1 += b1[j] * w2c[j];
            float c2 = 0.f; for (int j = 0; j < 50; j++) c2 += b2[j] * v1[j];
            float cb = bo[0];
            for (int j = 0; j < 30; j++) cb += bf1[j] * v2[j];
            for (int j = 0; j < 20; j++) cb += bf2[j] * v3[j];
            for (int j = 0; j < 10; j++) cb += bf3[j] * Wo[j];
            g_cst[0] = c1; g_cst[1] = c2; g_cst[2] = cb; cb_s = cb;
        }
        __syncthreads();
        if (t < G) out[t] = cb_s;
    }
}

// --- t0 = x . w1c : 4 lanes/node, 8 nodes/warp ------------------------------
__global__ void k_t0(const float* __restrict__ x, int n) {
    int gt    = blockIdx.x * blockDim.x + threadIdx.x;
    int w     = gt >> 5;
    int lane  = threadIdx.x & 31;
    int node  = w * 8 + (lane >> 2);
    int sub   = lane & 3;
    bool live = (node < n);
    int nc    = live ? node : (n - 1);

    const float4* xp = (const float4*)x + nc * 16 + sub * 4;
    float4 a = xp[0], b = xp[1], c = xp[2], d = xp[3];
    const float4* wv = (const float4*)g_w1c + sub * 4;
    float4 wa = wv[0], wb = wv[1], wc = wv[2], wd = wv[3];

    float s0 = a.x*wa.x + a.y*wa.y + a.z*wa.z + a.w*wa.w;
    float s1 = b.x*wb.x + b.y*wb.y + b.z*wb.z + b.w*wb.w;
    float s2 = c.x*wc.x + c.y*wc.y + c.z*wc.z + c.w*wc.w;
    float s3 = d.x*wd.x + d.y*wd.y + d.z*wd.z + d.w*wd.w;
    float acc = (s0 + s1) + (s2 + s3);

    acc += __shfl_xor_sync(0xffffffffu, acc, 1);
    acc += __shfl_xor_sync(0xffffffffu, acc, 2);

    if (live && sub == 0) g_ta[node] = acc;
}

// --- fill: counting-bucket edges by dst range (SMEM staged, block reserve) --
__global__ void k_fill(const void* ei, int E, unsigned magic) {
    __shared__ int2 stage[EPB];     // 32 KB
    __shared__ int  hist[NB];       // 2 KB (then reused as local cursor)
    __shared__ int  basec[NB];      // 2 KB
    int tid   = threadIdx.x;
    int start = blockIdx.x * EPB;
    int cnt   = min(EPB, E - start);
    if (cnt <= 0) return;

    for (int b = tid; b < NB; b += 256) hist[b] = 0;
    __syncthreads();

    for (int k = tid; k < cnt; k += 256) {
        int idx = start + k;
        int s, d;
        if (g_is64) {
            const long long* p = (const long long*)ei;
            s = (int)p[idx]; d = (int)p[E + idx];
        } else {
            const int* p = (const int*)ei;
            s = p[idx]; d = p[E + idx];
        }
        stage[k] = make_int2(s, d);
        atomicAdd(&hist[__umulhi((unsigned)d, magic)], 1);
    }
    __syncthreads();

    for (int b = tid; b < NB; b += 256) {
        int h = hist[b];
        basec[b] = h ? atomicAdd(&g_cur[b], h) : 0;
        hist[b] = 0;                 // reuse as local cursor
    }
    __syncthreads();

    for (int k = tid; k < cnt; k += 256) {
        int2 e  = stage[k];
        int  b  = __umulhi((unsigned)e.y, magic);
        int pos = basec[b] + atomicAdd(&hist[b], 1);
        if (pos < CAP) g_bedge[b * CAP + pos] = e;
    }
}

// --- per-bucket degree count -> dinv + p0 = dinv*t0 (dense writes) ----------
__global__ void k_degdinv(int n, int range) {
    __shared__ int cnt[256];
    int b    = blockIdx.x;
    int tid  = threadIdx.x;
    int base = b * range;
    int nn   = min(range, n - base);
    if (nn <= 0) return;
    cnt[tid] = 0;
    __syncthreads();
    int m = min(g_cur[b], CAP);
    for (int i = tid; i < m; i += 256)
        atomicAdd(&cnt[g_bedge[b * CAP + i].y - base], 1);
    __syncthreads();
    if (tid < nn) {
        int node = base + tid;
        float di = rsqrtf((float)(cnt[tid] + 1));
        g_dinv[node] = di;
        g_pa[node]   = di * g_ta[node];
    }
}

// --- layer 1: SMEM-accumulated aggregation + finalize (t1, p1) --------------
__global__ void k_agg1(int n, int range) {
    __shared__ float acc[256];
    int b    = blockIdx.x;
    int tid  = threadIdx.x;
    int base = b * range;
    int nn   = min(range, n - base);
    if (nn <= 0) return;
    acc[tid] = 0.f;
    __syncthreads();
    int m = min(g_cur[b], CAP);
    for (int i = tid; i < m; i += 256) {
        int2 e = g_bedge[b * CAP + i];
        atomicAdd(&acc[e.y - base], __ldg(&g_pa[e.x]));
    }
    __syncthreads();
    if (tid < nn) {
        int node = base + tid;
        float di = g_dinv[node];
        float t1 = di * (acc[tid] + di * g_ta[node]) + g_cst[0];
        g_tb[node] = t1;
        g_pb[node] = di * t1;
    }
}

// --- layer 2: aggregation + finalize + pooled sum per graph -----------------
__global__ void k_agg2pool(const void* batch, float* out, int n, int range) {
    __shared__ float acc[256];
    int b    = blockIdx.x;
    int tid  = threadIdx.x;
    int lane = tid & 31;
    int base = b * range;
    int nn   = min(range, n - base);
    if (nn <= 0) return;
    acc[tid] = 0.f;
    __syncthreads();
    int m = min(g_cur[b], CAP);
    for (int i = tid; i < m; i += 256) {
        int2 e = g_bedge[b * CAP + i];
        atomicAdd(&acc[e.y - base], __ldg(&g_pb[e.x]));
    }
    __syncthreads();

    int node = min(base + tid, n - 1);
    int gid  = g_is64 ? (int)((const long long*)batch)[node]
                      : ((const int*)batch)[node];
    float v = 0.f;
    if (tid < nn) {
        float di = g_dinv[node];
        v = di * (acc[tid] + di * g_tb[node]) + g_cst[1];
    }
    int g0   = __shfl_sync(0xffffffffu, gid, 0);
    bool uni = __all_sync(0xffffffffu, gid == g0);
    if (uni) {
        #pragma unroll
        for (int o = 16; o; o >>= 1) v += __shfl_xor_sync(0xffffffffu, v, o);
        if (lane == 0) atomicAdd(&out[g0], v);
    } else {
        atomicAdd(&out[gid], v);
    }
}

extern "C" void kernel_launch(void* const* d_in, const int* in_sizes, int n_in,
                              void* d_out, int out_size) {
    const float* x     = (const float*)d_in[0];
    const void*  ei    = d_in[1];
    const void*  batch = d_in[2];
    const float* W1  = (const float*)d_in[3],  *b1  = (const float*)d_in[4];
    const float* W2  = (const float*)d_in[5],  *b2  = (const float*)d_in[6];
    const float* Wf1 = (const float*)d_in[7],  *bf1 = (const float*)d_in[8];
    const float* Wf2 = (const float*)d_in[9],  *bf2 = (const float*)d_in[10];
    const float* Wf3 = (const float*)d_in[11], *bf3 = (const float*)d_in[12];
    const float* Wo  = (const float*)d_in[13], *bo  = (const float*)d_in[14];
    float* out = (float*)d_out;

    int E = in_sizes[1] / 2;
    int n = in_sizes[2];
    int G = out_size;

    int range = (n + NB - 1) / NB;                              // 196
    unsigned magic = (unsigned)(((1ull << 32) + range - 1) / (unsigned)range);

    k_init<<<2, 256>>>((const int*)ei, W1, b1, W2, b2,
                       Wf1, bf1, Wf2, bf2, Wf3, bf3, Wo, bo, out, G);
    k_t0<<<((n + 7) / 8 * 32 + 255) / 256, 256>>>(x, n);
    k_fill<<<(E + EPB - 1) / EPB, 256>>>(ei, E, magic);
    k_degdinv<<<NB, 256>>>(n, range);
    k_agg1<<<NB, 256>>>(n, range);
    k_agg2pool<<<NB, 256>>>(batch, out, n, range);
}